// round 16
// baseline (speedup 1.0000x reference)
#include <cuda_runtime.h>
#include <cstdint>

// Problem constants
#define KDIM 1024
#define NHEAD 16
#define DHEAD 64
#define NB 2
#define NT 2048
#define MROWS (NB * NT)   // 4096

// Scratch (static device globals — no allocation allowed).
// All values stored here are tf32-clean fp32 (low mantissa bits zero), so
// consumers can feed them to mma.sync without re-converting.
__device__ float g_Q[(size_t)MROWS * KDIM];          // [b,h,t,d]
__device__ float g_K[(size_t)MROWS * KDIM];          // [b,h,t,d]
__device__ float g_V[(size_t)MROWS * KDIM];          // [b,h,t,d]
__device__ float g_att[(size_t)MROWS * KDIM];        // [b*t, h*d]
__device__ float g_x[(size_t)MROWS * KDIM];          // tf32-clean x
__device__ float g_Wc[4][(size_t)KDIM * KDIM];       // tf32-clean Wq,Wk,Wv,Wo

// ---------------------------------------------------------------------------
// helpers
// ---------------------------------------------------------------------------
__device__ __forceinline__ uint32_t f2tf32(float x) {
    uint32_t r;
    asm("cvt.rna.tf32.f32 %0, %1;" : "=r"(r) : "f"(x));
    return r;
}

__device__ __forceinline__ void mma_tf32(float (&d)[4],
                                         const uint32_t (&a)[4],
                                         const uint32_t (&b)[2],
                                         const float (&c)[4]) {
    asm volatile(
        "mma.sync.aligned.m16n8k8.row.col.f32.tf32.tf32.f32 "
        "{%0,%1,%2,%3}, {%4,%5,%6,%7}, {%8,%9}, {%10,%11,%12,%13};\n"
        : "=f"(d[0]), "=f"(d[1]), "=f"(d[2]), "=f"(d[3])
        : "r"(a[0]), "r"(a[1]), "r"(a[2]), "r"(a[3]),
          "r"(b[0]), "r"(b[1]),
          "f"(c[0]), "f"(c[1]), "f"(c[2]), "f"(c[3]));
}

__device__ __forceinline__ void cp16(uint32_t smem_dst, const void* gsrc) {
    asm volatile("cp.async.cg.shared.global [%0], [%1], 16;\n"
                 :: "r"(smem_dst), "l"(gsrc));
}
#define CP_COMMIT() asm volatile("cp.async.commit_group;\n")
#define CP_WAIT0()  asm volatile("cp.async.wait_group 0;\n")
#define CP_WAIT1()  asm volatile("cp.async.wait_group 1;\n")

// ---------------------------------------------------------------------------
// prep: round x and the 4 weight matrices to tf32-clean fp32.
// ---------------------------------------------------------------------------
#define XV4 ((MROWS * KDIM) / 4)   // 1048576
#define WV4 ((KDIM * KDIM) / 4)    // 262144

__global__ void prep_kernel(const float* __restrict__ x,
                            const float* __restrict__ Wq, const float* __restrict__ Wk,
                            const float* __restrict__ Wv, const float* __restrict__ Wo)
{
    int i = blockIdx.x * blockDim.x + threadIdx.x;
    const float4* src;
    float4* dst;
    int idx;
    if (i < XV4) {
        src = (const float4*)x; dst = (float4*)g_x; idx = i;
    } else {
        int j = i - XV4;
        int w = j >> 18;            // /WV4
        idx = j & (WV4 - 1);
        const float* ws = (w == 0) ? Wq : (w == 1) ? Wk : (w == 2) ? Wv : Wo;
        src = (const float4*)ws; dst = (float4*)g_Wc[w];
    }
    float4 v = src[idx];
    float4 o;
    o.x = __uint_as_float(f2tf32(v.x));
    o.y = __uint_as_float(f2tf32(v.y));
    o.z = __uint_as_float(f2tf32(v.z));
    o.w = __uint_as_float(f2tf32(v.w));
    dst[idx] = o;
}

// ---------------------------------------------------------------------------
// tf32 mma GEMM: C[m,n] = sum_k A[m,k]*B[n,k]. Block 128x128x32, 256 thr,
// 8 warps 2(M)x4(N), warp tile 64x32, 3-stage cp.async pipeline.
// smem rows: pitch 32 words, 16B-chunk XOR swizzle (chunk ^= row&7) ->
// conflict-free fragment LDS and minimal smem.
// ---------------------------------------------------------------------------
#define GBM 128
#define GBN 128
#define GBK 32
#define GPITCH 32
#define GSTAGEW (GBM * GPITCH)                 // 4096 words per matrix stage
#define GSTAGES 3
#define GEMM_SMEM (2 * GSTAGES * GSTAGEW * 4)  // 98304 B

// word index of column cb within swizzled row
__device__ __forceinline__ int swz(int row, int cb) {
    return row * GPITCH + ((((cb >> 2) ^ row) & 7) << 2) + (cb & 3);
}

__device__ __forceinline__ void gemm_issue(uint32_t a_dst, uint32_t b_dst,
                                           const float* Ag, const float* Bg,
                                           int k0, int arow, int cbase)
{
#pragma unroll
    for (int q = 0; q < 4; q++) {
        int chunk = cbase + q;
        int sw    = (chunk ^ arow) & 7;
        cp16(a_dst + sw * 16, Ag + k0 + chunk * 4);
        cp16(b_dst + sw * 16, Bg + k0 + chunk * 4);
    }
    CP_COMMIT();
}

__device__ __forceinline__ void gemm_mma_core(
    const float* __restrict__ A, const float* __restrict__ B,
    float* sm, float (&acc)[4][4][4], int m0, int n0)
{
    const int tid  = threadIdx.x;
    const int lane = tid & 31;
    const int w    = tid >> 5;
    const int wm   = w >> 2;       // 0..1
    const int wn   = w & 3;        // 0..3
    const int gid  = lane >> 2;    // 0..7
    const int ctid = lane & 3;     // 0..3

    float* As = sm;                          // [GSTAGES][GSTAGEW]
    float* Bs = sm + GSTAGES * GSTAGEW;

    // cp.async mapping: thread -> row = tid>>1, chunks (tid&1)*4 .. +3
    const int arow  = tid >> 1;
    const int cbase = (tid & 1) * 4;
    const float* Ag = A + (size_t)(m0 + arow) * KDIM;
    const float* Bg = B + (size_t)(n0 + arow) * KDIM;
    const uint32_t As_u = (uint32_t)__cvta_generic_to_shared(As) + (arow * GPITCH) * 4;
    const uint32_t Bs_u = (uint32_t)__cvta_generic_to_shared(Bs) + (arow * GPITCH) * 4;

    const int NIT = KDIM / GBK;    // 32

    // prologue: issue stages 0 and 1
    gemm_issue(As_u, Bs_u, Ag, Bg, 0, arow, cbase);
    gemm_issue(As_u + GSTAGEW * 4, Bs_u + GSTAGEW * 4, Ag, Bg, GBK, arow, cbase);

    int s_cur = 0;   // stage of iteration i
    for (int i = 0; i < NIT; i++) {
        if (i < NIT - 1) { CP_WAIT1(); } else { CP_WAIT0(); }
        __syncthreads();

        if (i + 2 < NIT) {
            int s_nxt = s_cur + 2; if (s_nxt >= GSTAGES) s_nxt -= GSTAGES;
            gemm_issue(As_u + s_nxt * GSTAGEW * 4, Bs_u + s_nxt * GSTAGEW * 4,
                       Ag, Bg, (i + 2) * GBK, arow, cbase);
        }

        const float* Ac = As + s_cur * GSTAGEW;
        const float* Bc = Bs + s_cur * GSTAGEW;

#pragma unroll
        for (int kk = 0; kk < 4; kk++) {
            const int cb = kk * 8 + ctid;
            uint32_t a[4][4];
#pragma unroll
            for (int mt = 0; mt < 4; mt++) {
                int row = wm * 64 + mt * 16 + gid;
                a[mt][0] = __float_as_uint(Ac[swz(row, cb)]);
                a[mt][1] = __float_as_uint(Ac[swz(row + 8, cb)]);
                a[mt][2] = __float_as_uint(Ac[swz(row, cb + 4)]);
                a[mt][3] = __float_as_uint(Ac[swz(row + 8, cb + 4)]);
            }
            uint32_t b[4][2];
#pragma unroll
            for (int nt = 0; nt < 4; nt++) {
                int col = wn * 32 + nt * 8 + gid;
                b[nt][0] = __float_as_uint(Bc[swz(col, cb)]);
                b[nt][1] = __float_as_uint(Bc[swz(col, cb + 4)]);
            }
#pragma unroll
            for (int mt = 0; mt < 4; mt++)
#pragma unroll
                for (int nt = 0; nt < 4; nt++)
                    mma_tf32(acc[mt][nt], a[mt], b[nt], acc[mt][nt]);
        }

        s_cur += 1; if (s_cur >= GSTAGES) s_cur -= GSTAGES;
        __syncthreads();
    }
}

// QKV projection. WHICH: 0->g_Q 1->g_K 2->g_V; writes [b,h,t,d] tf32-clean.
template<int WHICH>
__global__ __launch_bounds__(256, 2)
void qkv_gemm_kernel()
{
    extern __shared__ float gsm[];
    float acc[4][4][4] = {};

    const int m0 = blockIdx.y * GBM;
    const int n0 = blockIdx.x * GBN;
    gemm_mma_core(g_x, g_Wc[WHICH], gsm, acc, m0, n0);

    float* C = (WHICH == 0) ? g_Q : (WHICH == 1) ? g_K : g_V;
    const int lane = threadIdx.x & 31;
    const int w    = threadIdx.x >> 5;
    const int wm   = w >> 2, wn = w & 3;
    const int gid  = lane >> 2, ctid = lane & 3;

#pragma unroll
    for (int mt = 0; mt < 4; mt++) {
#pragma unroll
        for (int nt = 0; nt < 4; nt++) {
            int n    = n0 + wn * 32 + nt * 8 + 2 * ctid;
            int head = n >> 6;
            int dd   = n & 63;
#pragma unroll
            for (int rr = 0; rr < 2; rr++) {
                int m  = m0 + wm * 64 + mt * 16 + gid + rr * 8;
                int bb = m >> 11;
                int tt = m & 2047;
                float2 v = make_float2(__uint_as_float(f2tf32(acc[mt][nt][rr * 2])),
                                       __uint_as_float(f2tf32(acc[mt][nt][rr * 2 + 1])));
                *(float2*)(C + ((size_t)((bb * NHEAD + head) * NT + tt)) * DHEAD + dd) = v;
            }
        }
    }
}

// Output projection: out = g_att @ Wo^T + bo (full fp32 epilogue).
__global__ __launch_bounds__(256, 2)
void out_gemm_kernel(const float* __restrict__ bias, float* __restrict__ out)
{
    extern __shared__ float gsm[];
    float acc[4][4][4] = {};

    const int m0 = blockIdx.y * GBM;
    const int n0 = blockIdx.x * GBN;
    gemm_mma_core(g_att, g_Wc[3], gsm, acc, m0, n0);

    const int lane = threadIdx.x & 31;
    const int w    = threadIdx.x >> 5;
    const int wm   = w >> 2, wn = w & 3;
    const int gid  = lane >> 2, ctid = lane & 3;

#pragma unroll
    for (int mt = 0; mt < 4; mt++) {
#pragma unroll
        for (int nt = 0; nt < 4; nt++) {
            int n = n0 + wn * 32 + nt * 8 + 2 * ctid;
            float b0 = bias[n], b1 = bias[n + 1];
#pragma unroll
            for (int rr = 0; rr < 2; rr++) {
                int m = m0 + wm * 64 + mt * 16 + gid + rr * 8;
                float2 v = make_float2(acc[mt][nt][rr * 2] + b0,
                                       acc[mt][nt][rr * 2 + 1] + b1);
                *(float2*)(out + (size_t)m * KDIM + n) = v;
            }
        }
    }
}

// ---------------------------------------------------------------------------
// Flash attention, tf32 mma. Block = (b, h, 64 q-rows), 128 threads (4 warps,
// 16 q-rows each -> warp-local softmax). Q A-fragments register-resident
// (pre-scaled by 1/8). K/V cp.async 2-stage double buffer. P re-fragmented
// via quad shuffles (no smem round-trip). Padding mask staged once as
// additive offsets.
// ---------------------------------------------------------------------------
#define KPITCH 68   // 4 mod 32 -> conflict-free K fragment LDS
#define VPITCH 72   // 8 mod 32 -> conflict-free V fragment LDS
#define FA_KW (64 * KPITCH)          // words per K stage
#define FA_VW (64 * VPITCH)          // words per V stage
#define FA_SMEM ((2 * FA_KW + 2 * FA_VW + NT) * 4)   // 79872 B

__global__ __launch_bounds__(128, 2)
void flash_attn_kernel(const int* __restrict__ padding)
{
    extern __shared__ float fsm[];
    float* Ksm  = fsm;                        // [2][FA_KW]
    float* Vsm  = fsm + 2 * FA_KW;            // [2][FA_VW]
    float* padm = fsm + 2 * FA_KW + 2 * FA_VW;// [NT]

    const int tid  = threadIdx.x;
    const int lane = tid & 31;
    const int warp = tid >> 5;      // 0..3
    const int gid  = lane >> 2;     // 0..7
    const int ctid = lane & 3;      // 0..3

    const int q0 = blockIdx.x * 64;
    const int h  = blockIdx.y;
    const int bb = blockIdx.z;

    const float* Qb = g_Q + ((size_t)(bb * NHEAD + h) * NT + q0) * DHEAD;
    const float* Kb = g_K + (size_t)(bb * NHEAD + h) * NT * DHEAD;
    const float* Vb = g_V + (size_t)(bb * NHEAD + h) * NT * DHEAD;
    const int*   pad = padding + bb * NT;

    // Q fragments in registers, pre-scaled by 1/sqrt(d)=0.125 (exact pow2).
    uint32_t aq[8][4];
    {
        const int r0 = warp * 16 + gid;
#pragma unroll
        for (int kk = 0; kk < 8; kk++) {
            int c = kk * 8 + ctid;
            aq[kk][0] = __float_as_uint(0.125f * Qb[(size_t)r0 * DHEAD + c]);
            aq[kk][1] = __float_as_uint(0.125f * Qb[(size_t)(r0 + 8) * DHEAD + c]);
            aq[kk][2] = __float_as_uint(0.125f * Qb[(size_t)r0 * DHEAD + c + 4]);
            aq[kk][3] = __float_as_uint(0.125f * Qb[(size_t)(r0 + 8) * DHEAD + c + 4]);
        }
    }

    // Padding mask as additive offsets (0 or -1e30), staged once.
#pragma unroll
    for (int j = 0; j < 16; j++) {
        int t = tid + j * 128;
        padm[t] = pad[t] ? 0.0f : -1e30f;
    }

    const uint32_t Ks_u = (uint32_t)__cvta_generic_to_shared(Ksm);
    const uint32_t Vs_u = (uint32_t)__cvta_generic_to_shared(Vsm);

    // cp.async mapping: 8 float4 per thread per tensor per tile
    const int frow = tid >> 4;          // 0..7 base row
    const int fc4  = (tid & 15) * 4;    // 0..60

    auto issue_kv = [&](int s, int kt) {
        const float* Kg = Kb + (size_t)kt * DHEAD;
        const float* Vg = Vb + (size_t)kt * DHEAD;
        uint32_t kd = Ks_u + (s * FA_KW) * 4;
        uint32_t vd = Vs_u + (s * FA_VW) * 4;
#pragma unroll
        for (int j = 0; j < 8; j++) {
            int r = frow + j * 8;
            cp16(kd + (r * KPITCH + fc4) * 4, Kg + (size_t)r * DHEAD + fc4);
            cp16(vd + (r * VPITCH + fc4) * 4, Vg + (size_t)r * DHEAD + fc4);
        }
        CP_COMMIT();
    };

    float o[8][4];
#pragma unroll
    for (int j = 0; j < 8; j++)
#pragma unroll
        for (int c = 0; c < 4; c++) o[j][c] = 0.0f;
    float m0r = -1e30f, m1r = -1e30f;
    float l0r = 0.0f,   l1r = 0.0f;

    issue_kv(0, 0);

    for (int i = 0; i < NT / 64; i++) {
        const int kt = i * 64;
        const int s  = i & 1;
        CP_WAIT0();
        __syncthreads();
        if (i + 1 < NT / 64) issue_kv((i + 1) & 1, kt + 64);

        const float* Kc = Ksm + s * FA_KW;
        const float* Vc = Vsm + s * FA_VW;

        // S = (Q/8) K^T : warp's 16 q-rows x 64 k-cols
        float sc[8][4];
#pragma unroll
        for (int j = 0; j < 8; j++)
#pragma unroll
            for (int c = 0; c < 4; c++) sc[j][c] = 0.0f;

#pragma unroll
        for (int kk = 0; kk < 8; kk++) {
            const int cb = kk * 8 + ctid;
#pragma unroll
            for (int j = 0; j < 8; j++) {
                uint32_t bk[2];
                const int col = j * 8 + gid;
                bk[0] = __float_as_uint(Kc[col * KPITCH + cb]);
                bk[1] = __float_as_uint(Kc[col * KPITCH + cb + 4]);
                mma_tf32(sc[j], aq[kk], bk, sc[j]);
            }
        }

        // mask + running max
        float mx0 = -1e30f, mx1 = -1e30f;
#pragma unroll
        for (int j = 0; j < 8; j++) {
            const int col = kt + j * 8 + 2 * ctid;
            float off0 = padm[col], off1 = padm[col + 1];
            sc[j][0] += off0;
            sc[j][1] += off1;
            sc[j][2] += off0;
            sc[j][3] += off1;
            mx0 = fmaxf(mx0, fmaxf(sc[j][0], sc[j][1]));
            mx1 = fmaxf(mx1, fmaxf(sc[j][2], sc[j][3]));
        }
        mx0 = fmaxf(mx0, __shfl_xor_sync(0xffffffffu, mx0, 1));
        mx0 = fmaxf(mx0, __shfl_xor_sync(0xffffffffu, mx0, 2));
        mx1 = fmaxf(mx1, __shfl_xor_sync(0xffffffffu, mx1, 1));
        mx1 = fmaxf(mx1, __shfl_xor_sync(0xffffffffu, mx1, 2));

        const float mn0 = fmaxf(m0r, mx0);
        const float mn1 = fmaxf(m1r, mx1);
        const float corr0 = __expf(m0r - mn0);
        const float corr1 = __expf(m1r - mn1);
        m0r = mn0; m1r = mn1;

        float rs0 = 0.0f, rs1 = 0.0f;
#pragma unroll
        for (int j = 0; j < 8; j++) {
            sc[j][0] = __expf(sc[j][0] - mn0);
            sc[j][1] = __expf(sc[j][1] - mn0);
            sc[j][2] = __expf(sc[j][2] - mn1);
            sc[j][3] = __expf(sc[j][3] - mn1);
            rs0 += sc[j][0] + sc[j][1];
            rs1 += sc[j][2] + sc[j][3];
        }
        rs0 += __shfl_xor_sync(0xffffffffu, rs0, 1);
        rs0 += __shfl_xor_sync(0xffffffffu, rs0, 2);
        rs1 += __shfl_xor_sync(0xffffffffu, rs1, 1);
        rs1 += __shfl_xor_sync(0xffffffffu, rs1, 2);
        l0r = l0r * corr0 + rs0;
        l1r = l1r * corr1 + rs1;

#pragma unroll
        for (int j = 0; j < 8; j++) {
            o[j][0] *= corr0; o[j][1] *= corr0;
            o[j][2] *= corr1; o[j][3] *= corr1;
        }

        // O += P V : re-fragment P via quad shuffles (acc layout -> A layout)
        const int qsrc0 = ctid >> 1;
        const int qsrc1 = qsrc0 + 2;
        const bool oddl = ctid & 1;
#pragma unroll
        for (int kk = 0; kk < 8; kk++) {
            float x0 = __shfl_sync(0xffffffffu, sc[kk][0], qsrc0, 4);
            float x1 = __shfl_sync(0xffffffffu, sc[kk][1], qsrc0, 4);
            float y0 = __shfl_sync(0xffffffffu, sc[kk][2], qsrc0, 4);
            float y1 = __shfl_sync(0xffffffffu, sc[kk][3], qsrc0, 4);
            float x2 = __shfl_sync(0xffffffffu, sc[kk][0], qsrc1, 4);
            float x3 = __shfl_sync(0xffffffffu, sc[kk][1], qsrc1, 4);
            float y2 = __shfl_sync(0xffffffffu, sc[kk][2], qsrc1, 4);
            float y3 = __shfl_sync(0xffffffffu, sc[kk][3], qsrc1, 4);
            uint32_t ap[4];
            ap[0] = f2tf32(oddl ? x1 : x0);
            ap[1] = f2tf32(oddl ? y1 : y0);
            ap[2] = f2tf32(oddl ? x3 : x2);
            ap[3] = f2tf32(oddl ? y3 : y2);
#pragma unroll
            for (int j = 0; j < 8; j++) {
                uint32_t bv[2];
                const int col = j * 8 + gid;
                bv[0] = __float_as_uint(Vc[(kk * 8 + ctid) * VPITCH + col]);
                bv[1] = __float_as_uint(Vc[(kk * 8 + ctid + 4) * VPITCH + col]);
                mma_tf32(o[j], ap, bv, o[j]);
            }
        }
    }

    // Epilogue: normalize, write tf32-clean [b*t, h*d]
    const float inv0 = 1.0f / l0r;
    const float inv1 = 1.0f / l1r;
    const int q = q0 + warp * 16 + gid;
#pragma unroll
    for (int j = 0; j < 8; j++) {
        const int d = j * 8 + 2 * ctid;
        float* dst0 = g_att + ((size_t)(bb * NT + q)) * KDIM + h * DHEAD + d;
        float* dst1 = g_att + ((size_t)(bb * NT + q + 8)) * KDIM + h * DHEAD + d;
        *(float2*)dst0 = make_float2(__uint_as_float(f2tf32(o[j][0] * inv0)),
                                     __uint_as_float(f2tf32(o[j][1] * inv0)));
        *(float2*)dst1 = make_float2(__uint_as_float(f2tf32(o[j][2] * inv1)),
                                     __uint_as_float(f2tf32(o[j][3] * inv1)));
    }
}

// ---------------------------------------------------------------------------
// Launch
// ---------------------------------------------------------------------------
extern "C" void kernel_launch(void* const* d_in, const int* in_sizes, int n_in,
                              void* d_out, int out_size)
{
    const float* x       = (const float*)d_in[0];
    const int*   padding = (const int*)  d_in[1];
    const float* Wq      = (const float*)d_in[2];
    const float* Wk      = (const float*)d_in[3];
    const float* Wv      = (const float*)d_in[4];
    const float* Wo      = (const float*)d_in[5];
    const float* bo      = (const float*)d_in[6];
    float*       out     = (float*)d_out;

    static bool init_done = false;
    if (!init_done) {
        cudaFuncSetAttribute(qkv_gemm_kernel<0>, cudaFuncAttributeMaxDynamicSharedMemorySize, GEMM_SMEM);
        cudaFuncSetAttribute(qkv_gemm_kernel<1>, cudaFuncAttributeMaxDynamicSharedMemorySize, GEMM_SMEM);
        cudaFuncSetAttribute(qkv_gemm_kernel<2>, cudaFuncAttributeMaxDynamicSharedMemorySize, GEMM_SMEM);
        cudaFuncSetAttribute(out_gemm_kernel,    cudaFuncAttributeMaxDynamicSharedMemorySize, GEMM_SMEM);
        cudaFuncSetAttribute(flash_attn_kernel,  cudaFuncAttributeMaxDynamicSharedMemorySize, FA_SMEM);
        init_done = true;
    }

    // 1) round inputs to tf32-clean fp32
    prep_kernel<<<(XV4 + 4 * WV4) / 256, 256>>>(x, Wq, Wk, Wv, Wo);

    // 2) QKV projections
    dim3 gemm_grid(KDIM / GBN, MROWS / GBM);   // (8, 32)
    qkv_gemm_kernel<0><<<gemm_grid, 256, GEMM_SMEM>>>();
    qkv_gemm_kernel<1><<<gemm_grid, 256, GEMM_SMEM>>>();
    qkv_gemm_kernel<2><<<gemm_grid, 256, GEMM_SMEM>>>();

    // 3) attention
    dim3 fa_grid(NT / 64, NHEAD, NB);          // (32, 16, 2)
    flash_attn_kernel<<<fa_grid, 128, FA_SMEM>>>(padding);

    // 4) output projection
    out_gemm_kernel<<<gemm_grid, 256, GEMM_SMEM>>>(bo, out);
}

// round 17
// speedup vs baseline: 1.6172x; 1.6172x over previous
#include <cuda_runtime.h>
#include <cuda_fp16.h>
#include <cstdint>

// Problem constants
#define KDIM 1024
#define NHEAD 16
#define DHEAD 64
#define NB 2
#define NT 2048
#define MROWS (NB * NT)   // 4096

// Scratch (static device globals — no allocation allowed). All fp16.
__device__ __half g_Qh[(size_t)MROWS * KDIM];    // [b,h,t,d], pre-scaled by 0.125
__device__ __half g_Kh[(size_t)MROWS * KDIM];    // [b,h,t,d]
__device__ __half g_Vth[(size_t)MROWS * KDIM];   // [b,h,d,t]  (transposed!)
__device__ __half g_atth[(size_t)MROWS * KDIM];  // [b*t, h*d]
__device__ __half g_xh[(size_t)MROWS * KDIM];    // fp16 x
__device__ __half g_Wh[4][(size_t)KDIM * KDIM];  // fp16 Wq,Wk,Wv,Wo

// ---------------------------------------------------------------------------
// helpers
// ---------------------------------------------------------------------------
__device__ __forceinline__ uint32_t h2u(__half2 h) {
    return *reinterpret_cast<uint32_t*>(&h);
}

__device__ __forceinline__ void mma_f16(float (&d)[4],
                                        const uint32_t (&a)[4],
                                        const uint32_t (&b)[2],
                                        const float (&c)[4]) {
    asm volatile(
        "mma.sync.aligned.m16n8k16.row.col.f32.f16.f16.f32 "
        "{%0,%1,%2,%3}, {%4,%5,%6,%7}, {%8,%9}, {%10,%11,%12,%13};\n"
        : "=f"(d[0]), "=f"(d[1]), "=f"(d[2]), "=f"(d[3])
        : "r"(a[0]), "r"(a[1]), "r"(a[2]), "r"(a[3]),
          "r"(b[0]), "r"(b[1]),
          "f"(c[0]), "f"(c[1]), "f"(c[2]), "f"(c[3]));
}

__device__ __forceinline__ void cp16(uint32_t smem_dst, const void* gsrc) {
    asm volatile("cp.async.cg.shared.global [%0], [%1], 16;\n"
                 :: "r"(smem_dst), "l"(gsrc));
}
#define CP_COMMIT() asm volatile("cp.async.commit_group;\n")
#define CP_WAIT0()  asm volatile("cp.async.wait_group 0;\n")
#define CP_WAIT1()  asm volatile("cp.async.wait_group 1;\n")
#define CP_WAIT2()  asm volatile("cp.async.wait_group 2;\n")

// ---------------------------------------------------------------------------
// prep: convert x and the 4 weight matrices to fp16.
// ---------------------------------------------------------------------------
#define XV4 ((MROWS * KDIM) / 4)   // 1048576
#define WV4 ((KDIM * KDIM) / 4)    // 262144

__global__ void prep_kernel(const float* __restrict__ x,
                            const float* __restrict__ Wq, const float* __restrict__ Wk,
                            const float* __restrict__ Wv, const float* __restrict__ Wo)
{
    int i = blockIdx.x * blockDim.x + threadIdx.x;
    const float4* src;
    __half* dst;
    int idx;
    if (i < XV4) {
        src = (const float4*)x; dst = g_xh; idx = i;
    } else {
        int j = i - XV4;
        int w = j >> 18;            // /WV4
        idx = j & (WV4 - 1);
        const float* ws = (w == 0) ? Wq : (w == 1) ? Wk : (w == 2) ? Wv : Wo;
        src = (const float4*)ws; dst = g_Wh[w];
    }
    float4 v = src[idx];
    __half2 lo = __floats2half2_rn(v.x, v.y);
    __half2 hi = __floats2half2_rn(v.z, v.w);
    uint2 o = make_uint2(h2u(lo), h2u(hi));
    *(uint2*)(dst + (size_t)idx * 4) = o;
}

// ---------------------------------------------------------------------------
// fp16 mma GEMM: C[m,n] = sum_k A[m,k]*B[n,k]. Block 128x128x32, 256 thr,
// 8 warps 2(M)x4(N), warp tile 64x32, m16n8k16, 4-stage cp.async.
// smem rows: pitch 40 halves (P/2=20 == 4 mod 8) -> conflict-free LDS.
// ---------------------------------------------------------------------------
#define GBM 128
#define GBN 128
#define GBKH 32                     // halves per k-tile
#define GP 40                       // pitch in halves
#define GSTW (GBM * GP)             // 5120 halves per matrix stage
#define GST 4
#define GEMM_SMEM (2 * GST * GSTW * 2)   // 81920 B

__device__ __forceinline__ void gemm_issue(uint32_t a_dst, uint32_t b_dst,
                                           const __half* Ag, const __half* Bg, int k0)
{
    cp16(a_dst,      Ag + k0);
    cp16(a_dst + 16, Ag + k0 + 8);
    cp16(b_dst,      Bg + k0);
    cp16(b_dst + 16, Bg + k0 + 8);
    CP_COMMIT();
}

__device__ __forceinline__ void gemm_mma_core(
    const __half* __restrict__ A, const __half* __restrict__ B,
    __half* sm, float (&acc)[4][4][4], int m0, int n0)
{
    const int tid  = threadIdx.x;
    const int lane = tid & 31;
    const int w    = tid >> 5;
    const int wm   = w >> 2;       // 0..1
    const int wn   = w & 3;        // 0..3
    const int gid  = lane >> 2;    // 0..7
    const int ctid = lane & 3;     // 0..3

    __half* As = sm;                         // [GST][GSTW]
    __half* Bs = sm + GST * GSTW;

    // cp.async mapping: row = tid>>1, halves offset (tid&1)*16 (+0, +8)
    const int arow = tid >> 1;
    const int hoff = (tid & 1) * 16;
    const __half* Ag = A + (size_t)(m0 + arow) * KDIM + hoff;
    const __half* Bg = B + (size_t)(n0 + arow) * KDIM + hoff;
    const uint32_t As_u = (uint32_t)__cvta_generic_to_shared(As) + (arow * GP + hoff) * 2;
    const uint32_t Bs_u = (uint32_t)__cvta_generic_to_shared(Bs) + (arow * GP + hoff) * 2;

    const int NIT = KDIM / GBKH;   // 32

    // prologue: issue stages 0,1,2
    gemm_issue(As_u,                Bs_u,                Ag, Bg, 0);
    gemm_issue(As_u + GSTW * 2,     Bs_u + GSTW * 2,     Ag, Bg, GBKH);
    gemm_issue(As_u + 2 * GSTW * 2, Bs_u + 2 * GSTW * 2, Ag, Bg, 2 * GBKH);

    int s_cur = 0;
    for (int i = 0; i < NIT; i++) {
        if (i < NIT - 2)      { CP_WAIT2(); }
        else if (i == NIT - 2){ CP_WAIT1(); }
        else                  { CP_WAIT0(); }
        __syncthreads();

        if (i + 3 < NIT) {
            int s_nxt = s_cur + 3; if (s_nxt >= GST) s_nxt -= GST;
            gemm_issue(As_u + s_nxt * GSTW * 2, Bs_u + s_nxt * GSTW * 2,
                       Ag, Bg, (i + 3) * GBKH);
        }

        const __half* Ac = As + s_cur * GSTW;
        const __half* Bc = Bs + s_cur * GSTW;

#pragma unroll
        for (int ks = 0; ks < 2; ks++) {
            const int cb = ks * 16 + 2 * ctid;
            uint32_t a[4][4];
#pragma unroll
            for (int mt = 0; mt < 4; mt++) {
                int row = wm * 64 + mt * 16 + gid;
                a[mt][0] = *(const uint32_t*)(Ac + row * GP + cb);
                a[mt][1] = *(const uint32_t*)(Ac + (row + 8) * GP + cb);
                a[mt][2] = *(const uint32_t*)(Ac + row * GP + cb + 8);
                a[mt][3] = *(const uint32_t*)(Ac + (row + 8) * GP + cb + 8);
            }
            uint32_t b[4][2];
#pragma unroll
            for (int nt = 0; nt < 4; nt++) {
                int col = wn * 32 + nt * 8 + gid;
                b[nt][0] = *(const uint32_t*)(Bc + col * GP + cb);
                b[nt][1] = *(const uint32_t*)(Bc + col * GP + cb + 8);
            }
#pragma unroll
            for (int mt = 0; mt < 4; mt++)
#pragma unroll
                for (int nt = 0; nt < 4; nt++)
                    mma_f16(acc[mt][nt], a[mt], b[nt], acc[mt][nt]);
        }

        s_cur += 1; if (s_cur >= GST) s_cur -= GST;
        __syncthreads();
    }
}

// Fused QKV projection: blockIdx.z selects 0->Q (pre-scaled), 1->K, 2->V(transposed).
__global__ __launch_bounds__(256, 2)
void qkv_gemm_kernel()
{
    extern __shared__ __half gsm[];
    float acc[4][4][4] = {};

    const int m0 = blockIdx.y * GBM;
    const int n0 = blockIdx.x * GBN;
    const int z  = blockIdx.z;
    gemm_mma_core(g_xh, g_Wh[z], gsm, acc, m0, n0);

    const int lane = threadIdx.x & 31;
    const int w    = threadIdx.x >> 5;
    const int wm   = w >> 2, wn = w & 3;
    const int gid  = lane >> 2, ctid = lane & 3;

    const float scale = (z == 0) ? 0.125f : 1.0f;

#pragma unroll
    for (int mt = 0; mt < 4; mt++) {
#pragma unroll
        for (int nt = 0; nt < 4; nt++) {
            int n    = n0 + wn * 32 + nt * 8 + 2 * ctid;
            int head = n >> 6;
            int dd   = n & 63;
#pragma unroll
            for (int rr = 0; rr < 2; rr++) {
                int m  = m0 + wm * 64 + mt * 16 + gid + rr * 8;
                int bb = m >> 11;
                int tt = m & 2047;
                float v0 = acc[mt][nt][rr * 2]     * scale;
                float v1 = acc[mt][nt][rr * 2 + 1] * scale;
                if (z == 2) {
                    // V transposed: [b,h,d,t]
                    size_t base = ((size_t)(bb * NHEAD + head) * DHEAD) * NT + tt;
                    g_Vth[base + (size_t)dd * NT]       = __float2half_rn(v0);
                    g_Vth[base + (size_t)(dd + 1) * NT] = __float2half_rn(v1);
                } else {
                    __half* C = (z == 0) ? g_Qh : g_Kh;
                    __half2 hv = __floats2half2_rn(v0, v1);
                    *(__half2*)(C + ((size_t)((bb * NHEAD + head) * NT + tt)) * DHEAD + dd) = hv;
                }
            }
        }
    }
}

// Output projection: out = g_atth @ Wo^T + bo (fp32 epilogue).
__global__ __launch_bounds__(256, 2)
void out_gemm_kernel(const float* __restrict__ bias, float* __restrict__ out)
{
    extern __shared__ __half gsm[];
    float acc[4][4][4] = {};

    const int m0 = blockIdx.y * GBM;
    const int n0 = blockIdx.x * GBN;
    gemm_mma_core(g_atth, g_Wh[3], gsm, acc, m0, n0);

    const int lane = threadIdx.x & 31;
    const int w    = threadIdx.x >> 5;
    const int wm   = w >> 2, wn = w & 3;
    const int gid  = lane >> 2, ctid = lane & 3;

#pragma unroll
    for (int mt = 0; mt < 4; mt++) {
#pragma unroll
        for (int nt = 0; nt < 4; nt++) {
            int n = n0 + wn * 32 + nt * 8 + 2 * ctid;
            float b0 = bias[n], b1 = bias[n + 1];
#pragma unroll
            for (int rr = 0; rr < 2; rr++) {
                int m = m0 + wm * 64 + mt * 16 + gid + rr * 8;
                float2 v = make_float2(acc[mt][nt][rr * 2] + b0,
                                       acc[mt][nt][rr * 2 + 1] + b1);
                *(float2*)(out + (size_t)m * KDIM + n) = v;
            }
        }
    }
}

// ---------------------------------------------------------------------------
// Flash attention, fp16 mma m16n8k16. Block = (b, h, 64 q-rows), 128 threads
// (4 warps, 16 q-rows each -> warp-local softmax). Q fragments register-
// resident (already scaled). K [t][d] and V^T [d][t] tiles via 3-stage
// cp.async. P: fp32 accumulators pack DIRECTLY into fp16 A-fragments
// (half2 of adjacent columns) — no shuffles, no smem round-trip.
// ---------------------------------------------------------------------------
#define FKP 72                       // pitch in halves (36 words == 4 mod 8)
#define FST 3
#define FSTW (64 * FKP)              // 4608 halves per tensor stage
#define FA_SMEM (2 * FST * FSTW * 2 + NT * 4)   // 55296 + 8192 = 63488 B

__global__ __launch_bounds__(128, 3)
void flash_attn_kernel(const int* __restrict__ padding)
{
    extern __shared__ char fsm[];
    __half* Ks  = (__half*)fsm;                       // [FST][FSTW]
    __half* Vts = Ks + FST * FSTW;                    // [FST][FSTW]
    float*  padm = (float*)(fsm + 2 * FST * FSTW * 2);// [NT]

    const int tid  = threadIdx.x;
    const int lane = tid & 31;
    const int warp = tid >> 5;      // 0..3
    const int gid  = lane >> 2;     // 0..7
    const int ctid = lane & 3;      // 0..3

    const int q0 = blockIdx.x * 64;
    const int h  = blockIdx.y;
    const int bb = blockIdx.z;

    const __half* Qb  = g_Qh + ((size_t)(bb * NHEAD + h) * NT + q0) * DHEAD;
    const __half* Kb  = g_Kh + (size_t)(bb * NHEAD + h) * NT * DHEAD;
    const __half* Vtb = g_Vth + (size_t)(bb * NHEAD + h) * DHEAD * NT;
    const int*    pad = padding + bb * NT;

    // Q fragments in registers (already scaled by 1/8 at projection).
    uint32_t aq[4][4];
    {
        const int r0 = warp * 16 + gid;
#pragma unroll
        for (int kk = 0; kk < 4; kk++) {
            int c = kk * 16 + 2 * ctid;
            aq[kk][0] = *(const uint32_t*)(Qb + (size_t)r0 * DHEAD + c);
            aq[kk][1] = *(const uint32_t*)(Qb + (size_t)(r0 + 8) * DHEAD + c);
            aq[kk][2] = *(const uint32_t*)(Qb + (size_t)r0 * DHEAD + c + 8);
            aq[kk][3] = *(const uint32_t*)(Qb + (size_t)(r0 + 8) * DHEAD + c + 8);
        }
    }

    // Padding mask as additive offsets, staged once.
#pragma unroll
    for (int j = 0; j < 16; j++) {
        int t = tid + j * 128;
        padm[t] = pad[t] ? 0.0f : -1e30f;
    }

    const uint32_t Ks_u  = (uint32_t)__cvta_generic_to_shared(Ks);
    const uint32_t Vts_u = (uint32_t)__cvta_generic_to_shared(Vts);

    // cp.async mapping: row = tid>>1 (0..63), halves offset (tid&1)*32
    const int frow = tid >> 1;
    const int fho  = (tid & 1) * 32;

    auto issue_kv = [&](int s, int kt) {
        const __half* Kg = Kb + (size_t)(kt + frow) * DHEAD + fho;
        const __half* Vg = Vtb + (size_t)frow * NT + kt + fho;
        uint32_t kd = Ks_u  + (s * FSTW + frow * FKP + fho) * 2;
        uint32_t vd = Vts_u + (s * FSTW + frow * FKP + fho) * 2;
#pragma unroll
        for (int q = 0; q < 4; q++) {
            cp16(kd + q * 16, Kg + q * 8);
            cp16(vd + q * 16, Vg + q * 8);
        }
        CP_COMMIT();
    };

    float o[8][4];
#pragma unroll
    for (int j = 0; j < 8; j++)
#pragma unroll
        for (int c = 0; c < 4; c++) o[j][c] = 0.0f;
    float m0r = -1e30f, m1r = -1e30f;
    float l0r = 0.0f,   l1r = 0.0f;

    const int NITF = NT / 64;   // 32
    issue_kv(0, 0);
    issue_kv(1, 64);

    int s_cur = 0;
    for (int i = 0; i < NITF; i++) {
        const int kt = i * 64;
        if (i < NITF - 1) { CP_WAIT1(); } else { CP_WAIT0(); }
        __syncthreads();
        if (i + 2 < NITF) {
            int s_nxt = s_cur + 2; if (s_nxt >= FST) s_nxt -= FST;
            issue_kv(s_nxt, kt + 128);
        }

        const __half* Kc  = Ks  + s_cur * FSTW;
        const __half* Vtc = Vts + s_cur * FSTW;

        // S = (Q/8) K^T : 16 q-rows x 64 k-cols per warp, k-dim = d = 64.
        float sc[8][4];
#pragma unroll
        for (int j = 0; j < 8; j++)
#pragma unroll
            for (int c = 0; c < 4; c++) sc[j][c] = 0.0f;

#pragma unroll
        for (int kk = 0; kk < 4; kk++) {
            const int cb = kk * 16 + 2 * ctid;
#pragma unroll
            for (int j = 0; j < 8; j++) {
                const int col = j * 8 + gid;
                uint32_t bk[2];
                bk[0] = *(const uint32_t*)(Kc + col * FKP + cb);
                bk[1] = *(const uint32_t*)(Kc + col * FKP + cb + 8);
                mma_f16(sc[j], aq[kk], bk, sc[j]);
            }
        }

        // mask + running max
        float mx0 = -1e30f, mx1 = -1e30f;
#pragma unroll
        for (int j = 0; j < 8; j++) {
            const int col = kt + j * 8 + 2 * ctid;
            float off0 = padm[col], off1 = padm[col + 1];
            sc[j][0] += off0;
            sc[j][1] += off1;
            sc[j][2] += off0;
            sc[j][3] += off1;
            mx0 = fmaxf(mx0, fmaxf(sc[j][0], sc[j][1]));
            mx1 = fmaxf(mx1, fmaxf(sc[j][2], sc[j][3]));
        }
        mx0 = fmaxf(mx0, __shfl_xor_sync(0xffffffffu, mx0, 1));
        mx0 = fmaxf(mx0, __shfl_xor_sync(0xffffffffu, mx0, 2));
        mx1 = fmaxf(mx1, __shfl_xor_sync(0xffffffffu, mx1, 1));
        mx1 = fmaxf(mx1, __shfl_xor_sync(0xffffffffu, mx1, 2));

        const float mn0 = fmaxf(m0r, mx0);
        const float mn1 = fmaxf(m1r, mx1);
        const float corr0 = __expf(m0r - mn0);
        const float corr1 = __expf(m1r - mn1);
        m0r = mn0; m1r = mn1;

        float rs0 = 0.0f, rs1 = 0.0f;
#pragma unroll
        for (int j = 0; j < 8; j++) {
            sc[j][0] = __expf(sc[j][0] - mn0);
            sc[j][1] = __expf(sc[j][1] - mn0);
            sc[j][2] = __expf(sc[j][2] - mn1);
            sc[j][3] = __expf(sc[j][3] - mn1);
            rs0 += sc[j][0] + sc[j][1];
            rs1 += sc[j][2] + sc[j][3];
        }
        rs0 += __shfl_xor_sync(0xffffffffu, rs0, 1);
        rs0 += __shfl_xor_sync(0xffffffffu, rs0, 2);
        rs1 += __shfl_xor_sync(0xffffffffu, rs1, 1);
        rs1 += __shfl_xor_sync(0xffffffffu, rs1, 2);
        l0r = l0r * corr0 + rs0;
        l1r = l1r * corr1 + rs1;

#pragma unroll
        for (int j = 0; j < 8; j++) {
            o[j][0] *= corr0; o[j][1] *= corr0;
            o[j][2] *= corr1; o[j][3] *= corr1;
        }

        // O += P V : fp32 acc pairs pack directly into fp16 A-fragments.
#pragma unroll
        for (int s4 = 0; s4 < 4; s4++) {
            uint32_t ap[4];
            ap[0] = h2u(__floats2half2_rn(sc[2 * s4][0],     sc[2 * s4][1]));
            ap[1] = h2u(__floats2half2_rn(sc[2 * s4][2],     sc[2 * s4][3]));
            ap[2] = h2u(__floats2half2_rn(sc[2 * s4 + 1][0], sc[2 * s4 + 1][1]));
            ap[3] = h2u(__floats2half2_rn(sc[2 * s4 + 1][2], sc[2 * s4 + 1][3]));
            const int cb = s4 * 16 + 2 * ctid;
#pragma unroll
            for (int j = 0; j < 8; j++) {
                const int col = j * 8 + gid;   // d-index block
                uint32_t bv[2];
                bv[0] = *(const uint32_t*)(Vtc + col * FKP + cb);
                bv[1] = *(const uint32_t*)(Vtc + col * FKP + cb + 8);
                mma_f16(o[j], ap, bv, o[j]);
            }
        }

        s_cur += 1; if (s_cur >= FST) s_cur -= FST;
    }

    // Epilogue: normalize, write fp16 [b*t, h*d]
    const float inv0 = 1.0f / l0r;
    const float inv1 = 1.0f / l1r;
    const int q = q0 + warp * 16 + gid;
#pragma unroll
    for (int j = 0; j < 8; j++) {
        const int d = j * 8 + 2 * ctid;
        __half* dst0 = g_atth + ((size_t)(bb * NT + q)) * KDIM + h * DHEAD + d;
        __half* dst1 = g_atth + ((size_t)(bb * NT + q + 8)) * KDIM + h * DHEAD + d;
        *(__half2*)dst0 = __floats2half2_rn(o[j][0] * inv0, o[j][1] * inv0);
        *(__half2*)dst1 = __floats2half2_rn(o[j][2] * inv1, o[j][3] * inv1);
    }
}

// ---------------------------------------------------------------------------
// Launch
// ---------------------------------------------------------------------------
extern "C" void kernel_launch(void* const* d_in, const int* in_sizes, int n_in,
                              void* d_out, int out_size)
{
    const float* x       = (const float*)d_in[0];
    const int*   padding = (const int*)  d_in[1];
    const float* Wq      = (const float*)d_in[2];
    const float* Wk      = (const float*)d_in[3];
    const float* Wv      = (const float*)d_in[4];
    const float* Wo      = (const float*)d_in[5];
    const float* bo      = (const float*)d_in[6];
    float*       out     = (float*)d_out;

    static bool init_done = false;
    if (!init_done) {
        cudaFuncSetAttribute(qkv_gemm_kernel,   cudaFuncAttributeMaxDynamicSharedMemorySize, GEMM_SMEM);
        cudaFuncSetAttribute(out_gemm_kernel,   cudaFuncAttributeMaxDynamicSharedMemorySize, GEMM_SMEM);
        cudaFuncSetAttribute(flash_attn_kernel, cudaFuncAttributeMaxDynamicSharedMemorySize, FA_SMEM);
        init_done = true;
    }

    // 1) convert inputs to fp16
    prep_kernel<<<(XV4 + 4 * WV4) / 256, 256>>>(x, Wq, Wk, Wv, Wo);

    // 2) QKV projections (fused: z = 0/1/2)
    dim3 qkv_grid(KDIM / GBN, MROWS / GBM, 3);   // (8, 32, 3)
    qkv_gemm_kernel<<<qkv_grid, 256, GEMM_SMEM>>>();

    // 3) attention
    dim3 fa_grid(NT / 64, NHEAD, NB);            // (32, 16, 2)
    flash_attn_kernel<<<fa_grid, 128, FA_SMEM>>>(padding);

    // 4) output projection
    dim3 gemm_grid(KDIM / GBN, MROWS / GBM);     // (8, 32)
    out_gemm_kernel<<<gemm_grid, 256, GEMM_SMEM>>>(bo, out);
}